// round 17
// baseline (speedup 1.0000x reference)
#include <cuda_runtime.h>
#include <cuda_fp16.h>
#include <math.h>
#include <stdint.h>

#define NN   50000
#define NE   800000
#define FIN  1433
#define KPAD1 1440
#define KT1  90            // KPAD1/16
#define KT2  16            // FHID/16
#define NRB  3125          // NN/16 row-blocks (exact)
#define FHID 256
#define FOUT 128
#define NCLS 7
#define BN_EPS 1e-5f

// ---------------- scratch (device globals; no runtime allocation) ----------------
__device__ int   g_cnt[NN];
__device__ int   g_offs[NN + 1];
__device__ int   g_cur[NN];
__device__ int   g_bsum[64];
__device__ int2  g_csr[NE];
__device__ float g_dinv[NN];
__device__ float g_invdeg[NN];
__device__ __half2 g_xh[(size_t)NRB * KT1 * 128];     // x, fragment-permuted fp16 tiles
__device__ __half2 g_w1p[(size_t)KT1 * 2 * 1024];     // W1 fragment-permuted (2 nblks)
__device__ __half2 g_w2p[(size_t)KT2 * 1 * 1024];     // W2 fragment-permuted (1 nblk)
__device__ __half2 g_h1h[(size_t)NN * (FHID / 2)];    // x @ W1, fp16 linear rows
__device__ __half2 g_act1h[(size_t)NRB * KT2 * 128];  // ELU(BN(agg1)), fragment-permuted fp16
__device__ __half2 g_h2h[(size_t)NN * (FOUT / 2)];    // act1 @ W2, fp16 linear rows

// ================= helpers =================
__device__ __forceinline__ uint32_t smem_u32(const void* p) {
    uint32_t a;
    asm("{ .reg .u64 t; cvta.to.shared.u64 t, %1; cvt.u32.u64 %0, t; }" : "=r"(a) : "l"(p));
    return a;
}

__device__ __forceinline__ void cp16(uint32_t dst, const void* src, int srcsize) {
    asm volatile("cp.async.cg.shared.global [%0], [%1], 16, %2;"
                 :: "r"(dst), "l"(src), "r"(srcsize) : "memory");
}

__device__ __forceinline__ void mma_f16(float* c, const uint32_t* a, const uint32_t* b) {
    asm volatile(
        "mma.sync.aligned.m16n8k16.row.col.f32.f16.f16.f32 "
        "{%0,%1,%2,%3}, {%4,%5,%6,%7}, {%8,%9}, {%0,%1,%2,%3};"
        : "+f"(c[0]), "+f"(c[1]), "+f"(c[2]), "+f"(c[3])
        : "r"(a[0]), "r"(a[1]), "r"(a[2]), "r"(a[3]), "r"(b[0]), "r"(b[1]));
}

// ================= preprocessing =================
// x -> fp16 fragment-permuted tiles
__global__ __launch_bounds__(256)
void pad_xh_kernel(const float* __restrict__ x) {
    int idx = blockIdx.x * blockDim.x + threadIdx.x;
    if (idx >= NRB * KT1 * 32) return;
    int lane = idx & 31;
    int tile = idx >> 5;
    int kt = tile % KT1;
    int rb = tile / KT1;
    int g = lane >> 2, tig = lane & 3;
    int row0 = rb * 16 + g;
    int k0 = kt * 16 + 2 * tig;
    const float* xr0 = x + (size_t)row0 * FIN;
    const float* xr1 = xr0 + (size_t)8 * FIN;

    float a0 = (k0     < FIN) ? xr0[k0]     : 0.0f;
    float a1 = (k0 + 1 < FIN) ? xr0[k0 + 1] : 0.0f;
    float b0 = (k0     < FIN) ? xr1[k0]     : 0.0f;
    float b1 = (k0 + 1 < FIN) ? xr1[k0 + 1] : 0.0f;
    int k8 = k0 + 8;
    float a2 = (k8     < FIN) ? xr0[k8]     : 0.0f;
    float a3 = (k8 + 1 < FIN) ? xr0[k8 + 1] : 0.0f;
    float b2 = (k8     < FIN) ? xr1[k8]     : 0.0f;
    float b3 = (k8 + 1 < FIN) ? xr1[k8 + 1] : 0.0f;

    __half2* dstp = g_xh + (size_t)tile * 128 + lane * 4;
    dstp[0] = __floats2half2_rn(a0, a1);
    dstp[1] = __floats2half2_rn(b0, b1);
    dstp[2] = __floats2half2_rn(a2, a3);
    dstp[3] = __floats2half2_rn(b2, b3);
}

// W [K, NGN] row-major -> fragment-permuted 4096B blocks per (nblk, kt)
template <int KT, int KVALID, int NGN>
__global__ void pack_w_kernel(const float* __restrict__ W, __half2* __restrict__ out) {
    constexpr int NBLKS = NGN / 128;
    int idx = blockIdx.x * blockDim.x + threadIdx.x;
    if (idx >= KT * NBLKS * 256) return;
    int c = idx & 255;
    int block = idx >> 8;
    int kt = block % KT;
    int nblk = block / KT;
    int nhalf = c >> 7;
    int c2 = c & 127;
    int q = c2 >> 5;
    int lane = c2 & 31;
    int g = lane >> 2, tig = lane & 3;
    int col0 = nblk * 128 + nhalf * 64 + (2 * q) * 8 + g;
    int col1 = col0 + 8;
    int kb = kt * 16 + 2 * tig;

    auto rd = [&](int k, int col) -> float {
        return (k < KVALID) ? W[(size_t)k * NGN + col] : 0.0f;
    };

    __half2* dst = out + (size_t)block * 1024 + c * 4;
    dst[0] = __floats2half2_rn(rd(kb,     col0), rd(kb + 1, col0));
    dst[1] = __floats2half2_rn(rd(kb + 8, col0), rd(kb + 9, col0));
    dst[2] = __floats2half2_rn(rd(kb,     col1), rd(kb + 1, col1));
    dst[3] = __floats2half2_rn(rd(kb + 8, col1), rd(kb + 9, col1));
}

// ================= CSR build =================
__global__ void zero_cnt_kernel() {
    int i = blockIdx.x * blockDim.x + threadIdx.x;
    if (i < NN) g_cnt[i] = 0;
}

__global__ void count_deg_kernel(const int* __restrict__ dst) {
    int e = blockIdx.x * blockDim.x + threadIdx.x;
    if (e < NE) atomicAdd(&g_cnt[dst[e]], 1);
}

__global__ __launch_bounds__(1024)
void scan_block_kernel() {
    __shared__ int ws[32];
    int t = threadIdx.x, b = blockIdx.x;
    int i = b * 1024 + t;
    int v = (i < NN) ? g_cnt[i] : 0;
    if (i < NN) {
        float d = (float)v + 1.0f;
        g_dinv[i]   = rsqrtf(d);
        g_invdeg[i] = 1.0f / d;
    }
    int lane = t & 31, w = t >> 5;
    int x = v;
    #pragma unroll
    for (int o = 1; o < 32; o <<= 1) {
        int y = __shfl_up_sync(0xffffffffu, x, o);
        if (lane >= o) x += y;
    }
    if (lane == 31) ws[w] = x;
    __syncthreads();
    if (w == 0) {
        int s = ws[lane];
        #pragma unroll
        for (int o = 1; o < 32; o <<= 1) {
            int y = __shfl_up_sync(0xffffffffu, s, o);
            if (lane >= o) s += y;
        }
        ws[lane] = s;
    }
    __syncthreads();
    int pre = (w > 0) ? ws[w - 1] : 0;
    if (i < NN) g_offs[i] = pre + x - v;
    if (t == 1023) g_bsum[b] = pre + x;
}

__global__ void scan_bsum_kernel(int nblk) {
    __shared__ int s[64];
    int t = threadIdx.x;
    s[t] = (t < nblk) ? g_bsum[t] : 0;
    __syncthreads();
    if (t == 0) {
        int acc = 0;
        for (int i = 0; i < nblk; i++) { int v = s[i]; s[i] = acc; acc += v; }
    }
    __syncthreads();
    if (t < nblk) g_bsum[t] = s[t];
}

__global__ __launch_bounds__(1024)
void scan_add_kernel() {
    int t = threadIdx.x, b = blockIdx.x;
    int i = b * 1024 + t;
    if (i < NN) {
        int o = g_offs[i] + g_bsum[b];
        g_offs[i] = o;
        g_cur[i]  = o;
    }
    if (i == 0) g_offs[NN] = NE;
}

__global__ void fill_csr_kernel(const int* __restrict__ src, const int* __restrict__ dst) {
    int e = blockIdx.x * blockDim.x + threadIdx.x;
    if (e < NE) {
        int s = src[e];
        int d = dst[e];
        int p = atomicAdd(&g_cur[d], 1);
        g_csr[p] = make_int2(s, __float_as_int(g_dinv[s] * g_dinv[d]));
    }
}

// ================= fp16 GEMM (m16n8k16, fragment-permuted A AND B) =================
template <int KT, int NCH2>
__global__ __launch_bounds__(256, 2)
void gemm_fp16_kernel(const __half2* __restrict__ At, const __half2* __restrict__ Bw,
                      __half2* __restrict__ Co) {
    constexpr int S = 8;
    constexpr int A_BYTES = 4096;
    constexpr int STG_B = 8192;
    static_assert(KT % 2 == 0, "KT even");

    extern __shared__ char sm[];
    uint32_t smb = smem_u32(sm);

    int tid = threadIdx.x, lane = tid & 31, w = tid >> 5;
    int wm = (w & 3) * 32;
    int wn = (w >> 2) * 64;
    int m0 = blockIdx.y * 128;
    int n0 = blockIdx.x * 128;

    int a_tl = tid >> 5;
    int a_rb = (m0 >> 4) + a_tl;
    bool a_ok = (a_rb < NRB);
    int a_rbs = a_ok ? a_rb : 0;
    uint32_t a_dst0 = smb + (uint32_t)(a_tl * 512 + (tid & 31) * 16);
    uint32_t b_dst0 = smb + (uint32_t)(A_BYTES + tid * 16);

    float c[2][8][4];
    #pragma unroll
    for (int mt = 0; mt < 2; mt++)
        #pragma unroll
        for (int nt = 0; nt < 8; nt++)
            #pragma unroll
            for (int q = 0; q < 4; q++) c[mt][nt][q] = 0.0f;

    auto load_stage = [&](int kt, int slot) {
        uint32_t off = (uint32_t)(slot * STG_B);
        const char* asrc = (const char*)At + ((size_t)a_rbs * KT + kt) * 512 + (tid & 31) * 16;
        cp16(a_dst0 + off, asrc, a_ok ? 16 : 0);
        const char* bsrc = (const char*)Bw + ((size_t)(blockIdx.x * KT + kt)) * 4096 + tid * 16;
        cp16(b_dst0 + off, bsrc, 16);
    };

    auto process = [&](int kt) {
        uint32_t As = smb + (uint32_t)((kt & 7) * STG_B);
        uint32_t Bs = As + A_BYTES;
        uint32_t a[2][4], b[8][2];
        #pragma unroll
        for (int mt = 0; mt < 2; mt++) {
            uint32_t addr = As + (uint32_t)(((wm >> 4) + mt) * 512 + lane * 16);
            asm volatile("ld.shared.v4.b32 {%0,%1,%2,%3}, [%4];"
                : "=r"(a[mt][0]), "=r"(a[mt][1]), "=r"(a[mt][2]), "=r"(a[mt][3]) : "r"(addr));
        }
        uint32_t bb = Bs + (uint32_t)((wn >> 6) * 2048 + lane * 16);
        #pragma unroll
        for (int q = 0; q < 4; q++) {
            asm volatile("ld.shared.v4.b32 {%0,%1,%2,%3}, [%4];"
                : "=r"(b[2 * q][0]), "=r"(b[2 * q][1]),
                  "=r"(b[2 * q + 1][0]), "=r"(b[2 * q + 1][1])
                : "r"(bb + q * 512));
        }
        #pragma unroll
        for (int mt = 0; mt < 2; mt++)
            #pragma unroll
            for (int nt = 0; nt < 8; nt++)
                mma_f16(c[mt][nt], a[mt], b[nt]);
    };

    #pragma unroll
    for (int s = 0; s < 6; s++) {
        if (s < KT) load_stage(s, s);
        asm volatile("cp.async.commit_group;" ::: "memory");
    }

    for (int kt = 0; kt < KT; kt += 2) {
        asm volatile("cp.async.wait_group 4;" ::: "memory");
        __syncthreads();

        if (kt + 6 < KT) load_stage(kt + 6, (kt + 6) & 7);
        asm volatile("cp.async.commit_group;" ::: "memory");
        if (kt + 7 < KT) load_stage(kt + 7, (kt + 7) & 7);
        asm volatile("cp.async.commit_group;" ::: "memory");

        process(kt);
        process(kt + 1);
    }

    #pragma unroll
    for (int mt = 0; mt < 2; mt++) {
        int r0 = m0 + wm + mt * 16 + (lane >> 2);
        #pragma unroll
        for (int nt = 0; nt < 8; nt++) {
            int colh = ((n0 + wn + nt * 8) >> 1) + (lane & 3);
            if (r0 < NN)
                Co[(size_t)r0 * NCH2 + colh] = __floats2half2_rn(c[mt][nt][0], c[mt][nt][1]);
            if (r0 + 8 < NN)
                Co[(size_t)(r0 + 8) * NCH2 + colh] = __floats2half2_rn(c[mt][nt][2], c[mt][nt][3]);
        }
    }
}

// ================= fused aggregate + bias + BN + ELU (layer 1, fp16 in/out) =================
// One block = one row-block: 16 warps = 16 nodes; smem-staged coalesced
// fragment-tile output (replaces the scatter-store tail).
__device__ __forceinline__ float elu1(float x) { return x > 0.0f ? x : expm1f(x); }

__device__ __forceinline__ void acc8_h(float* acc, uint4 v, float cc) {
    float2 f0 = __half22float2(*(__half2*)&v.x);
    float2 f1 = __half22float2(*(__half2*)&v.y);
    float2 f2 = __half22float2(*(__half2*)&v.z);
    float2 f3 = __half22float2(*(__half2*)&v.w);
    acc[0] += f0.x * cc; acc[1] += f0.y * cc;
    acc[2] += f1.x * cc; acc[3] += f1.y * cc;
    acc[4] += f2.x * cc; acc[5] += f2.y * cc;
    acc[6] += f3.x * cc; acc[7] += f3.y * cc;
}

__global__ __launch_bounds__(512)
void aggregate1_kernel(const float* __restrict__ bias,
                       const float* __restrict__ bnw, const float* __restrict__ bnb,
                       const float* __restrict__ bnm, const float* __restrict__ bnv) {
    __shared__ __half2 stage[16 * 132];   // 132 half2 stride: bank-conflict-free reads

    int wid = threadIdx.x >> 5;   // 0..15 (node-in-rb, later tile kt)
    int lane = threadIdx.x & 31;
    int rb = blockIdx.x;          // 0..NRB-1 (NN == NRB*16 exactly)
    int node = rb * 16 + wid;

    float acc[8];
    {
        uint4 v = ((const uint4*)g_h1h)[(size_t)node * 32 + lane];
        float idg = g_invdeg[node];
        #pragma unroll
        for (int q = 0; q < 8; q++) acc[q] = 0.0f;
        acc8_h(acc, v, idg);
    }

    int beg = g_offs[node];
    int end = g_offs[node + 1];
    int j = beg;
    for (; j + 4 <= end; j += 4) {
        int2 e0 = g_csr[j], e1 = g_csr[j + 1], e2 = g_csr[j + 2], e3 = g_csr[j + 3];
        uint4 v0 = ((const uint4*)g_h1h)[(size_t)e0.x * 32 + lane];
        uint4 v1 = ((const uint4*)g_h1h)[(size_t)e1.x * 32 + lane];
        uint4 v2 = ((const uint4*)g_h1h)[(size_t)e2.x * 32 + lane];
        uint4 v3 = ((const uint4*)g_h1h)[(size_t)e3.x * 32 + lane];
        acc8_h(acc, v0, __int_as_float(e0.y));
        acc8_h(acc, v1, __int_as_float(e1.y));
        acc8_h(acc, v2, __int_as_float(e2.y));
        acc8_h(acc, v3, __int_as_float(e3.y));
    }
    for (; j < end; j++) {
        int2 e = g_csr[j];
        uint4 v = ((const uint4*)g_h1h)[(size_t)e.x * 32 + lane];
        acc8_h(acc, v, __int_as_float(e.y));
    }

    float ov[8];
    int f = lane * 8;
    #pragma unroll
    for (int t = 0; t < 2; t++) {
        int ff = f + t * 4;
        float4 bb = *(const float4*)(bias + ff);
        float4 w  = *(const float4*)(bnw + ff);
        float4 b2 = *(const float4*)(bnb + ff);
        float4 mn = *(const float4*)(bnm + ff);
        float4 vr = *(const float4*)(bnv + ff);
        ov[t * 4 + 0] = elu1((acc[t * 4 + 0] + bb.x - mn.x) * rsqrtf(vr.x + BN_EPS) * w.x + b2.x);
        ov[t * 4 + 1] = elu1((acc[t * 4 + 1] + bb.y - mn.y) * rsqrtf(vr.y + BN_EPS) * w.y + b2.y);
        ov[t * 4 + 2] = elu1((acc[t * 4 + 2] + bb.z - mn.z) * rsqrtf(vr.z + BN_EPS) * w.z + b2.z);
        ov[t * 4 + 3] = elu1((acc[t * 4 + 3] + bb.w - mn.w) * rsqrtf(vr.w + BN_EPS) * w.w + b2.w);
    }

    // stage: row = wid, feature half2 idx = lane*4 .. lane*4+3 (contiguous STS)
    {
        __half2* srow = stage + wid * 132 + lane * 4;
        srow[0] = __floats2half2_rn(ov[0], ov[1]);
        srow[1] = __floats2half2_rn(ov[2], ov[3]);
        srow[2] = __floats2half2_rn(ov[4], ov[5]);
        srow[3] = __floats2half2_rn(ov[6], ov[7]);
    }
    __syncthreads();

    // cooperative coalesced permuted-tile write: thread -> tile kt=wid, chunk=lane
    // tile(rb,kt) half2 position lane*4 + j holds:
    //   row = g + 8*(j&1), feat-half2 = kt*8 + tig + 4*(j>>1)   (pad_xh convention)
    {
        int kt = wid;
        int g = lane >> 2, tig = lane & 3;
        __half2 v0 = stage[(g    ) * 132 + kt * 8 + tig];
        __half2 v1 = stage[(g + 8) * 132 + kt * 8 + tig];
        __half2 v2 = stage[(g    ) * 132 + kt * 8 + tig + 4];
        __half2 v3 = stage[(g + 8) * 132 + kt * 8 + tig + 4];
        uint4 pack;
        pack.x = *(uint32_t*)&v0; pack.y = *(uint32_t*)&v1;
        pack.z = *(uint32_t*)&v2; pack.w = *(uint32_t*)&v3;
        ((uint4*)(g_act1h + ((size_t)rb * KT2 + kt) * 128))[lane] = pack;
    }
}

// ===== layer 2 aggregate + BN + ELU, fused with softmax head =====
__device__ __forceinline__ void acc4_h(float4& acc, uint2 v, float cc) {
    float2 f0 = __half22float2(*(__half2*)&v.x);
    float2 f1 = __half22float2(*(__half2*)&v.y);
    acc.x += f0.x * cc; acc.y += f0.y * cc;
    acc.z += f1.x * cc; acc.w += f1.y * cc;
}

__global__ __launch_bounds__(256)
void aggregate2_head_kernel(const float* __restrict__ bias,
                            const float* __restrict__ bnw, const float* __restrict__ bnb,
                            const float* __restrict__ bnm, const float* __restrict__ bnv,
                            const float* __restrict__ Wp, const float* __restrict__ bp,
                            float* __restrict__ out_h, float* __restrict__ out_z) {
    constexpr int F = FOUT;
    __shared__ float sW[F * NCLS];
    __shared__ float sbp[NCLS];
    for (int i = threadIdx.x; i < F * NCLS; i += blockDim.x) sW[i] = Wp[i];
    if (threadIdx.x < NCLS) sbp[threadIdx.x] = bp[threadIdx.x];
    __syncthreads();

    const uint2* h = (const uint2*)g_h2h;
    int warp = (blockIdx.x * blockDim.x + threadIdx.x) >> 5;
    int lane = threadIdx.x & 31;
    if (warp >= NN) return;
    int node = warp;

    float4 acc = make_float4(0.f, 0.f, 0.f, 0.f);
    acc4_h(acc, h[(size_t)node * 32 + lane], g_invdeg[node]);

    int beg = g_offs[node];
    int end = g_offs[node + 1];
    int j = beg;
    for (; j + 4 <= end; j += 4) {
        int2 e0 = g_csr[j], e1 = g_csr[j + 1], e2 = g_csr[j + 2], e3 = g_csr[j + 3];
        uint2 v0 = h[(size_t)e0.x * 32 + lane];
        uint2 v1 = h[(size_t)e1.x * 32 + lane];
        uint2 v2 = h[(size_t)e2.x * 32 + lane];
        uint2 v3 = h[(size_t)e3.x * 32 + lane];
        acc4_h(acc, v0, __int_as_float(e0.y));
        acc4_h(acc, v1, __int_as_float(e1.y));
        acc4_h(acc, v2, __int_as_float(e2.y));
        acc4_h(acc, v3, __int_as_float(e3.y));
    }
    for (; j < end; j++) {
        int2 e = g_csr[j];
        acc4_h(acc, h[(size_t)e.x * 32 + lane], __int_as_float(e.y));
    }

    int f = lane * 4;
    float4 bb = *(const float4*)(bias + f);
    float4 w  = *(const float4*)(bnw + f);
    float4 b2 = *(const float4*)(bnb + f);
    float4 mn = *(const float4*)(bnm + f);
    float4 vr = *(const float4*)(bnv + f);
    float4 o;
    o.x = elu1((acc.x + bb.x - mn.x) * rsqrtf(vr.x + BN_EPS) * w.x + b2.x);
    o.y = elu1((acc.y + bb.y - mn.y) * rsqrtf(vr.y + BN_EPS) * w.y + b2.y);
    o.z = elu1((acc.z + bb.z - mn.z) * rsqrtf(vr.z + BN_EPS) * w.z + b2.z);
    o.w = elu1((acc.w + bb.w - mn.w) * rsqrtf(vr.w + BN_EPS) * w.w + b2.w);
    ((float4*)(out_h + (size_t)node * F))[lane] = o;

    float p[NCLS];
    #pragma unroll
    for (int k = 0; k < NCLS; k++)
        p[k] = o.x * sW[(f + 0) * NCLS + k] + o.y * sW[(f + 1) * NCLS + k]
             + o.z * sW[(f + 2) * NCLS + k] + o.w * sW[(f + 3) * NCLS + k];
    #pragma unroll
    for (int off = 16; off > 0; off >>= 1)
        #pragma unroll
        for (int k = 0; k < NCLS; k++)
            p[k] += __shfl_xor_sync(0xffffffffu, p[k], off);

    #pragma unroll
    for (int k = 0; k < NCLS; k++) p[k] += sbp[k];
    float m = p[0];
    #pragma unroll
    for (int k = 1; k < NCLS; k++) m = fmaxf(m, p[k]);
    float ssum = 0.0f;
    #pragma unroll
    for (int k = 0; k < NCLS; k++) { p[k] = expf(p[k] - m); ssum += p[k]; }
    float inv = 1.0f / ssum;
    if (lane < NCLS) out_z[(size_t)node * NCLS + lane] = p[lane] * inv;
}

// ================= host =================
extern "C" void kernel_launch(void* const* d_in, const int* in_sizes, int n_in,
                              void* d_out, int out_size) {
    const float* x    = (const float*)d_in[0];
    const int*   ei   = (const int*)d_in[1];
    const float* W1   = (const float*)d_in[2];
    const float* b1   = (const float*)d_in[3];
    const float* bn1w = (const float*)d_in[4];
    const float* bn1b = (const float*)d_in[5];
    const float* bn1m = (const float*)d_in[6];
    const float* bn1v = (const float*)d_in[7];
    const float* W2   = (const float*)d_in[8];
    const float* b2   = (const float*)d_in[9];
    const float* bn2w = (const float*)d_in[10];
    const float* bn2b = (const float*)d_in[11];
    const float* bn2m = (const float*)d_in[12];
    const float* bn2v = (const float*)d_in[13];
    const float* Wp   = (const float*)d_in[14];
    const float* bp   = (const float*)d_in[15];

    const int* src = ei;
    const int* dst = ei + NE;

    float* out_h = (float*)d_out;
    float* out_z = out_h + (size_t)NN * FOUT;

    void *p_xh, *p_w1p, *p_w2p, *p_act1h, *p_h1h, *p_h2h;
    cudaGetSymbolAddress(&p_xh,    g_xh);
    cudaGetSymbolAddress(&p_w1p,   g_w1p);
    cudaGetSymbolAddress(&p_w2p,   g_w2p);
    cudaGetSymbolAddress(&p_act1h, g_act1h);
    cudaGetSymbolAddress(&p_h1h,   g_h1h);
    cudaGetSymbolAddress(&p_h2h,   g_h2h);

    constexpr int SMEM_G = 8 * 8192;   // 65536 (S=8, 8KB/stage)

    static cudaStream_t s_side = nullptr;
    static cudaEvent_t ev_fork, ev_join, ev_w1;
    if (!s_side) {
        cudaStreamCreateWithFlags(&s_side, cudaStreamNonBlocking);
        cudaEventCreateWithFlags(&ev_fork, cudaEventDisableTiming);
        cudaEventCreateWithFlags(&ev_join, cudaEventDisableTiming);
        cudaEventCreateWithFlags(&ev_w1, cudaEventDisableTiming);
        cudaFuncSetAttribute(gemm_fp16_kernel<KT1, FHID / 2>,
                             cudaFuncAttributeMaxDynamicSharedMemorySize, SMEM_G);
        cudaFuncSetAttribute(gemm_fp16_kernel<KT2, FOUT / 2>,
                             cudaFuncAttributeMaxDynamicSharedMemorySize, SMEM_G);
    }

    const int NODE_BLKS = (NN + 255) / 256;
    const int EDGE_BLKS = (NE + 255) / 256;
    const int SCAN_BLKS = (NN + 1023) / 1024;
    const int MTILES    = (NN + 127) / 128;   // 391
    const int XH_THREADS = NRB * KT1 * 32;

    // ---- fork ----
    cudaEventRecord(ev_fork, 0);
    cudaStreamWaitEvent(s_side, ev_fork, 0);

    // enqueue order: #0 pad_xh (main), #1 pack_w1 (side), #2 zero (side), #3 GEMM1 (main)
    pad_xh_kernel<<<(XH_THREADS + 255) / 256, 256>>>(x);
    pack_w_kernel<KT1, FIN, FHID><<<(KT1 * 2 * 256 + 255) / 256, 256, 0, s_side>>>(W1, (__half2*)p_w1p);
    cudaEventRecord(ev_w1, s_side);
    zero_cnt_kernel<<<NODE_BLKS, 256, 0, s_side>>>();

    cudaStreamWaitEvent(0, ev_w1, 0);
    gemm_fp16_kernel<KT1, FHID / 2><<<dim3(2, MTILES), 256, SMEM_G>>>(
        (const __half2*)p_xh, (const __half2*)p_w1p, (__half2*)p_h1h);

    // rest of CSR build + W2 packing on side stream
    count_deg_kernel<<<EDGE_BLKS, 256, 0, s_side>>>(dst);
    scan_block_kernel<<<SCAN_BLKS, 1024, 0, s_side>>>();
    scan_bsum_kernel<<<1, 64, 0, s_side>>>(SCAN_BLKS);
    scan_add_kernel<<<SCAN_BLKS, 1024, 0, s_side>>>();
    fill_csr_kernel<<<EDGE_BLKS, 256, 0, s_side>>>(src, dst);
    pack_w_kernel<KT2, FHID, FOUT><<<(KT2 * 1 * 256 + 255) / 256, 256, 0, s_side>>>(W2, (__half2*)p_w2p);
    cudaEventRecord(ev_join, s_side);

    // ---- join: aggregation needs CSR ----
    cudaStreamWaitEvent(0, ev_join, 0);

    aggregate1_kernel<<<NRB, 512>>>(b1, bn1w, bn1b, bn1m, bn1v);

    gemm_fp16_kernel<KT2, FOUT / 2><<<dim3(1, MTILES), 256, SMEM_G>>>(
        (const __half2*)p_act1h, (const __half2*)p_w2p, (__half2*)p_h2h);

    aggregate2_head_kernel<<<(NN * 32 + 255) / 256, 256>>>(b2, bn2w, bn2b, bn2m, bn2v,
                                                           Wp, bp, out_h, out_z);
}